// round 12
// baseline (speedup 1.0000x reference)
#include <cuda_runtime.h>
#include <cuda_bf16.h>
#include <cuda_fp16.h>
#include <cstdint>

#define CB 8
#define CN 1024
#define PD 128
#define CH 64
#define CJ 256
#define CXD 64

// ---------------- device scratch ----------------
__device__ __half g_Qf16[CH * CJ * PD];     // scale 0.125*log2(e) folded in
__device__ __half g_posF16[CB * CN * PD];
__device__ __half g_xF16[CB * CN * CXD];
__device__ __half g_Wf16[4096 * 64];
__device__ __half g_Of16[CB * CJ * CH * CXD];

// ---------------- helpers ----------------
__device__ __forceinline__ uint32_t smem_u32(const void* p) {
    uint32_t a;
    asm("{ .reg .u64 t; cvta.to.shared.u64 t, %1; cvt.u32.u64 %0, t; }"
        : "=r"(a) : "l"(p));
    return a;
}
#define CP16(dst, src) \
    asm volatile("cp.async.cg.shared.global [%0], [%1], 16;" :: "r"(dst), "l"(src))
#define CP_COMMIT() asm volatile("cp.async.commit_group;" ::: "memory")
#define CP_WAIT(n)  asm volatile("cp.async.wait_group %0;" :: "n"(n) : "memory")

__device__ __forceinline__ void ldsm4(uint32_t a, uint32_t& r0, uint32_t& r1,
                                      uint32_t& r2, uint32_t& r3) {
    asm volatile("ldmatrix.sync.aligned.m8n8.x4.shared.b16 {%0,%1,%2,%3}, [%4];"
                 : "=r"(r0), "=r"(r1), "=r"(r2), "=r"(r3) : "r"(a));
}
__device__ __forceinline__ void ldsm4t(uint32_t a, uint32_t& r0, uint32_t& r1,
                                       uint32_t& r2, uint32_t& r3) {
    asm volatile("ldmatrix.sync.aligned.m8n8.x4.trans.shared.b16 {%0,%1,%2,%3}, [%4];"
                 : "=r"(r0), "=r"(r1), "=r"(r2), "=r"(r3) : "r"(a));
}
// fp16 mma
__device__ __forceinline__ void mma16816h(float* d, const uint32_t* a,
                                          uint32_t b0, uint32_t b1) {
    asm volatile(
        "mma.sync.aligned.m16n8k16.row.col.f32.f16.f16.f32 "
        "{%0,%1,%2,%3}, {%4,%5,%6,%7}, {%8,%9}, {%0,%1,%2,%3};"
        : "+f"(d[0]), "+f"(d[1]), "+f"(d[2]), "+f"(d[3])
        : "r"(a[0]), "r"(a[1]), "r"(a[2]), "r"(a[3]), "r"(b0), "r"(b1));
}

// ---------------- prep: pos, x, W_out -> fp16 ; out <- bias ----------------
__global__ void prep_all(const float* __restrict__ pos, const float* __restrict__ x,
                         const float* __restrict__ W_out,
                         const float* __restrict__ b_out, float* __restrict__ out) {
    int bi = blockIdx.x;
    if (bi < 1024) {
        int i = bi * 256 + threadIdx.x;          // 262144 float4s of pos
        float4 v = ((const float4*)pos)[i];
        ((__half2*)g_posF16)[i * 2]     = __floats2half2_rn(v.x, v.y);
        ((__half2*)g_posF16)[i * 2 + 1] = __floats2half2_rn(v.z, v.w);
    } else if (bi < 1536) {
        int i = (bi - 1024) * 256 + threadIdx.x; // 131072 float4s of x
        float4 v = ((const float4*)x)[i];
        ((__half2*)g_xF16)[i * 2]     = __floats2half2_rn(v.x, v.y);
        ((__half2*)g_xF16)[i * 2 + 1] = __floats2half2_rn(v.z, v.w);
    } else if (bi < 1792) {
        int i = (bi - 1536) * 256 + threadIdx.x; // 65536 float4s of W_out
        float4 v = ((const float4*)W_out)[i];
        ((__half2*)g_Wf16)[i * 2]     = __floats2half2_rn(v.x, v.y);
        ((__half2*)g_Wf16)[i * 2 + 1] = __floats2half2_rn(v.z, v.w);
    } else {
        int idx = (bi - 1792) * 256 + threadIdx.x;   // 131072 out elements
        out[idx] = b_out[idx & 63];
    }
}

// ---------------- k2: K2[h][j][k] = s * W_q[k, h*64+e] k_lat[j,e] -> fp16 ----
// s = 0.125 * log2(e) so attn can use exp2 directly.
__global__ void k2_kernel(const float* __restrict__ W_q,
                          const float* __restrict__ k_lat) {
    __shared__ float sW[128 * 68];
    const int jblk = blockIdx.x, h = blockIdx.y;
    const int tid = threadIdx.x;
    const int lane = tid & 31, w = tid >> 5;
#pragma unroll
    for (int it = 0; it < 8; it++) {
        int f4 = tid + it * 256;
        int k = f4 >> 4, e4 = f4 & 15;
        float4 v = *(const float4*)(W_q + k * 4096 + h * 64 + e4 * 4);
        *(float4*)(sW + k * 68 + e4 * 4) = v;
    }
    __syncthreads();
#pragma unroll
    for (int jc = 0; jc < 8; jc++) {
        int j = jblk * 64 + w * 8 + jc;
        float a0 = 0.f, a1 = 0.f, a2 = 0.f, a3 = 0.f;
#pragma unroll
        for (int e = 0; e < 64; e += 4) {
            float4 kl = *(const float4*)(k_lat + j * 64 + e);
            float4 w0 = *(const float4*)(sW + (lane)      * 68 + e);
            float4 w1 = *(const float4*)(sW + (lane + 32) * 68 + e);
            float4 w2 = *(const float4*)(sW + (lane + 64) * 68 + e);
            float4 w3 = *(const float4*)(sW + (lane + 96) * 68 + e);
            a0 += w0.x * kl.x + w0.y * kl.y + w0.z * kl.z + w0.w * kl.w;
            a1 += w1.x * kl.x + w1.y * kl.y + w1.z * kl.z + w1.w * kl.w;
            a2 += w2.x * kl.x + w2.y * kl.y + w2.z * kl.z + w2.w * kl.w;
            a3 += w3.x * kl.x + w3.y * kl.y + w3.z * kl.z + w3.w * kl.w;
        }
        const float s = 0.18033688f;   // 0.125 * log2(e)
        int base = (h * CJ + j) * PD;
        g_Qf16[base + lane]      = __float2half_rn(a0 * s);
        g_Qf16[base + lane + 32] = __float2half_rn(a1 * s);
        g_Qf16[base + lane + 64] = __float2half_rn(a2 * s);
        g_Qf16[base + lane + 96] = __float2half_rn(a3 * s);
    }
}

// ---------------- attention: all-fp16 single-pass S and PV ----------------
#define KROW 272
#define XROW 144
#define KSTG 34816                 // 128 * 272
#define XSTG 18432                 // 128 * 144 (single fp16)
#define OKST(s) ((s) * KSTG)
#define OXST(s) (104448 + (s) * XSTG)
#define O_Q   159744               // dedicated Q region
#define SMEM_BYTES 194560          // O_Q + KSTG

__device__ __forceinline__ void prefetch_g(uint32_t sb, int st, int b, int n0, int tid) {
    uint32_t kbase = sb + OKST(st);
    const __half* kp = g_posF16 + (size_t)(b * CN + n0) * PD;
#pragma unroll
    for (int it = 0; it < 4; it++) {
        int idx = tid + it * 512;
        int row = idx >> 4, q = idx & 15;
        CP16(kbase + row * KROW + q * 16, kp + row * PD + q * 8);
    }
    uint32_t xbase = sb + OXST(st);
    const __half* xp = g_xF16 + (size_t)(b * CN + n0) * CXD;
#pragma unroll
    for (int it = 0; it < 2; it++) {
        int idx = tid + it * 512;
        int row = idx >> 3, q = idx & 7;
        CP16(xbase + row * XROW + q * 16, xp + row * CXD + q * 8);
    }
}

__global__ __launch_bounds__(512, 1)
void attn_kernel() {
    extern __shared__ char smc[];
    const uint32_t sb = smem_u32(smc);
    const int tid = threadIdx.x;
    const int lane = tid & 31, w = tid >> 5;
    const int wm = w & 7, half = w >> 3;
    const int jt = blockIdx.x, h = blockIdx.y, b = blockIdx.z;
    const int m0 = wm * 16;
    const int g = lane >> 2, t = lane & 3;

    const int arow = (lane & 7) + ((lane >> 3) & 1) * 8;
    const int acol = ((lane >> 4) & 1) * 16;
    const int brow = (lane & 7) + ((lane >> 4) & 1) * 8;
    const int bcol = ((lane >> 3) & 1) * 16;
    const int xrow = (lane & 7) + ((lane >> 3) & 1) * 8;
    const int xcol = ((lane >> 4) & 1) * 16;

    // ---- prologue: stage Q, prefetch G0/G1 ----
    {
        const __half* qp = g_Qf16 + (size_t)(h * CJ + jt * 128) * PD;
#pragma unroll
        for (int it = 0; it < 4; it++) {
            int idx = tid + it * 512;
            int row = idx >> 4, q = idx & 15;
            CP16(sb + O_Q + row * KROW + q * 16, qp + row * PD + q * 8);
        }
        CP_COMMIT();
        prefetch_g(sb, 0, b, 0, tid);
        CP_COMMIT();
        prefetch_g(sb, 1, b, 128, tid);
        CP_COMMIT();
    }
    CP_WAIT(2);
    __syncthreads();
    uint32_t qA[8][4];
    {
        uint32_t qb = sb + O_Q + (m0 + arow) * KROW + acol;
#pragma unroll
        for (int ks = 0; ks < 8; ks++)
            ldsm4(qb + ks * 32, qA[ks][0], qA[ks][1], qA[ks][2], qA[ks][3]);
    }

    float oacc[8][4];
#pragma unroll
    for (int i = 0; i < 8; i++)
#pragma unroll
        for (int r = 0; r < 4; r++) oacc[i][r] = 0.f;
    float rs0 = 0.f, rs1 = 0.f;

    for (int ch = 0; ch < 8; ch++) {
        if (ch < 7) { CP_WAIT(1); } else { CP_WAIT(0); }
        __syncthreads();     // data visible; all warps past chunk ch-1
        if (ch + 2 < 8) {
            prefetch_g(sb, (ch + 2) % 3, b, (ch + 2) * 128, tid);
            CP_COMMIT();
        }

        const uint32_t kb = sb + OKST(ch % 3) + (half * 64 + brow) * KROW + bcol;
        const uint32_t xbase = sb + OXST(ch % 3);

        float sc[2][8];

        // S slab 0
#pragma unroll
        for (int r = 0; r < 8; r++) sc[0][r] = 0.f;
#pragma unroll
        for (int ks = 0; ks < 8; ks++) {
            uint32_t k0, k1, k2, k3;
            ldsm4(kb + ks * 32, k0, k1, k2, k3);
            mma16816h(sc[0],     qA[ks], k0, k1);
            mma16816h(sc[0] + 4, qA[ks], k2, k3);
        }

#pragma unroll
        for (int np = 0; np < 4; np++) {
            const int cur = np & 1, nxt = cur ^ 1;
            // issue next slab's S-MMAs first: tensor stays busy during exp(np)
            if (np < 3) {
#pragma unroll
                for (int r = 0; r < 8; r++) sc[nxt][r] = 0.f;
#pragma unroll
                for (int ks = 0; ks < 8; ks++) {
                    uint32_t k0, k1, k2, k3;
                    ldsm4(kb + (np + 1) * (16 * KROW) + ks * 32, k0, k1, k2, k3);
                    mma16816h(sc[nxt],     qA[ks], k0, k1);
                    mma16816h(sc[nxt] + 4, qA[ks], k2, k3);
                }
            }
            // epilogue of slab np: exp2 -> fp16 P frags (log2e folded in Q scale)
            float p0 = exp2f(sc[cur][0]);
            float p1 = exp2f(sc[cur][1]);
            float p2 = exp2f(sc[cur][2]);
            float p3 = exp2f(sc[cur][3]);
            float p4 = exp2f(sc[cur][4]);
            float p5 = exp2f(sc[cur][5]);
            float p6 = exp2f(sc[cur][6]);
            float p7 = exp2f(sc[cur][7]);
            rs0 += p0 + p1 + p4 + p5;
            rs1 += p2 + p3 + p6 + p7;
            uint32_t ph[4];
            __half2 h0 = __floats2half2_rn(p0, p1);
            __half2 h1 = __floats2half2_rn(p2, p3);
            __half2 h2 = __floats2half2_rn(p4, p5);
            __half2 h3 = __floats2half2_rn(p6, p7);
            ph[0] = *reinterpret_cast<uint32_t*>(&h0);
            ph[1] = *reinterpret_cast<uint32_t*>(&h1);
            ph[2] = *reinterpret_cast<uint32_t*>(&h2);
            ph[3] = *reinterpret_cast<uint32_t*>(&h3);
            // PV single pass fp16
            uint32_t xb = xbase + (half * 64 + np * 16 + xrow) * XROW + xcol;
#pragma unroll
            for (int xt = 0; xt < 4; xt++) {
                uint32_t x0, x1, x2, x3;
                ldsm4t(xb + xt * 32, x0, x1, x2, x3);
                mma16816h(oacc[2 * xt],     ph, x0, x1);
                mma16816h(oacc[2 * xt + 1], ph, x2, x3);
            }
        }
    }
    __syncthreads();   // compute done; low smem reusable for exchange

    // ---- pair reduction across warp halves ----
    rs0 += __shfl_xor_sync(0xffffffffu, rs0, 1);
    rs0 += __shfl_xor_sync(0xffffffffu, rs0, 2);
    rs1 += __shfl_xor_sync(0xffffffffu, rs1, 1);
    rs1 += __shfl_xor_sync(0xffffffffu, rs1, 2);

    float* exO = (float*)smc;                 // [8][32][32]
    float* exR = (float*)(smc + 32768);       // [8][16]
    if (half == 1) {
#pragma unroll
        for (int xt = 0; xt < 8; xt++) {
#pragma unroll
            for (int r = 0; r < 4; r++)
                exO[(wm * 32 + lane) * 32 + xt * 4 + r] = oacc[xt][r];
        }
        if (t == 0) {
            exR[wm * 16 + g] = rs0;
            exR[wm * 16 + 8 + g] = rs1;
        }
    }
    __syncthreads();
    if (half == 0) {
        float inv0 = 1.0f / (rs0 + exR[wm * 16 + g]);
        float inv1 = 1.0f / (rs1 + exR[wm * 16 + 8 + g]);
        int j0 = jt * 128 + m0 + g;
        __half* ob = g_Of16 + (size_t)(b * CJ + j0) * (CH * CXD) + h * CXD;
#pragma unroll
        for (int xt = 0; xt < 8; xt++) {
            int col = xt * 8 + 2 * t;
            float b0 = exO[(wm * 32 + lane) * 32 + xt * 4 + 0];
            float b1 = exO[(wm * 32 + lane) * 32 + xt * 4 + 1];
            float b2 = exO[(wm * 32 + lane) * 32 + xt * 4 + 2];
            float b3 = exO[(wm * 32 + lane) * 32 + xt * 4 + 3];
            __half2 v0 = __floats2half2_rn((oacc[xt][0] + b0) * inv0,
                                           (oacc[xt][1] + b1) * inv0);
            __half2 v1 = __floats2half2_rn((oacc[xt][2] + b2) * inv1,
                                           (oacc[xt][3] + b3) * inv1);
            *(__half2*)(ob + col) = v0;
            *(__half2*)(ob + 8 * (CH * CXD) + col) = v1;
        }
    }
}

// ---------------- out = O @ W + b (fp16 tensor cores, k-split x8) ----------------
#define AROW 144
#define WROW 144
#define OA_BYTES (128 * AROW)      // 18432
#define OW_BYTES (64 * WROW)       // 9216
#define OSTG (OA_BYTES + OW_BYTES) // 27648
#define OUT_SMEM_BYTES (2 * OSTG)  // 55296

__device__ __forceinline__ void out_prefetch(uint32_t sb, int st, int r0, int k0, int tid) {
    uint32_t ab = sb + st * OSTG;
#pragma unroll
    for (int it = 0; it < 4; it++) {
        int idx = tid + it * 256;        // 1024: 128 rows x 8 x 16B
        int row = idx >> 3, q = idx & 7;
        CP16(ab + row * AROW + q * 16, g_Of16 + (size_t)(r0 + row) * 4096 + k0 + q * 8);
    }
    uint32_t wb = ab + OA_BYTES;
#pragma unroll
    for (int it = 0; it < 2; it++) {
        int idx = tid + it * 256;        // 512: 64 k-rows x 8 x 16B
        int row = idx >> 3, q = idx & 7;
        CP16(wb + row * WROW + q * 16, g_Wf16 + (size_t)(k0 + row) * 64 + q * 8);
    }
}

__global__ __launch_bounds__(256, 1)
void out_kernel(float* __restrict__ out) {
    extern __shared__ char osmc[];
    const uint32_t sb = smem_u32(osmc);
    const int r0 = blockIdx.x * 128, ksl = blockIdx.y;
    const int tid = threadIdx.x;
    const int lane = tid & 31, w = tid >> 5;
    const int m0 = w * 16;
    const int g = lane >> 2, t = lane & 3;

    const int arow = (lane & 7) + ((lane >> 3) & 1) * 8;
    const int acol = ((lane >> 4) & 1) * 16;
    const int xrow = (lane & 7) + ((lane >> 3) & 1) * 8;
    const int xcol = ((lane >> 4) & 1) * 16;

    out_prefetch(sb, 0, r0, ksl * 512, tid);
    CP_COMMIT();

    float oacc[8][4];
#pragma unroll
    for (int i = 0; i < 8; i++)
#pragma unroll
        for (int r = 0; r < 4; r++) oacc[i][r] = 0.f;

    for (int sub = 0; sub < 8; sub++) {
        const int st = sub & 1;
        CP_WAIT(0);
        __syncthreads();
        if (sub + 1 < 8) {
            out_prefetch(sb, st ^ 1, r0, ksl * 512 + (sub + 1) * 64, tid);
            CP_COMMIT();
        }
        uint32_t abase = sb + st * OSTG + (m0 + arow) * AROW + acol;
        uint32_t wbase = sb + st * OSTG + OA_BYTES + xrow * WROW + xcol;
#pragma unroll
        for (int ks = 0; ks < 4; ks++) {
            uint32_t A[4];
            ldsm4(abase + ks * 32, A[0], A[1], A[2], A[3]);
#pragma unroll
            for (int ct = 0; ct < 4; ct++) {
                uint32_t x0, x1, x2, x3;
                ldsm4t(wbase + ks * (16 * WROW) + ct * 32, x0, x1, x2, x3);
                mma16816h(oacc[2 * ct],     A, x0, x1);
                mma16816h(oacc[2 * ct + 1], A, x2, x3);
            }
        }
        __syncthreads();
    }

    int r = r0 + m0 + g;
#pragma unroll
    for (int i = 0; i < 8; i++) {
        int c = i * 8 + 2 * t;
        atomicAdd(out + (size_t)r * 64 + c,           oacc[i][0]);
        atomicAdd(out + (size_t)r * 64 + c + 1,       oacc[i][1]);
        atomicAdd(out + (size_t)(r + 8) * 64 + c,     oacc[i][2]);
        atomicAdd(out + (size_t)(r + 8) * 64 + c + 1, oacc[i][3]);
    }
}

// ---------------------------------------------------------------------------
extern "C" void kernel_launch(void* const* d_in, const int* in_sizes, int n_in,
                              void* d_out, int out_size) {
    (void)in_sizes; (void)n_in; (void)out_size;
    const float* pos   = (const float*)d_in[0];
    const float* x     = (const float*)d_in[1];
    const float* W_q   = (const float*)d_in[2];
    const float* k_lat = (const float*)d_in[3];
    const float* W_out = (const float*)d_in[4];
    const float* b_out = (const float*)d_in[5];
    float* out = (float*)d_out;

    cudaFuncSetAttribute(attn_kernel, cudaFuncAttributeMaxDynamicSharedMemorySize,
                         SMEM_BYTES);
    cudaFuncSetAttribute(out_kernel, cudaFuncAttributeMaxDynamicSharedMemorySize,
                         OUT_SMEM_BYTES);

    prep_all<<<2304, 256>>>(pos, x, W_out, b_out, out);
    k2_kernel<<<dim3(4, 64), 256>>>(W_q, k_lat);
    attn_kernel<<<dim3(2, CH, CB), 512, SMEM_BYTES>>>();
    out_kernel<<<dim3(16, 8), 256, OUT_SMEM_BYTES>>>(out);
}

// round 14
// speedup vs baseline: 1.0177x; 1.0177x over previous
#include <cuda_runtime.h>
#include <cuda_bf16.h>
#include <cuda_fp16.h>
#include <cstdint>

#define CB 8
#define CN 1024
#define PD 128
#define CH 64
#define CJ 256
#define CXD 64

// ---------------- device scratch ----------------
__device__ __half g_Qf16[CH * CJ * PD];     // scale 0.125*log2(e) folded in
__device__ __half g_posF16[CB * CN * PD];
__device__ __half g_xF16[CB * CN * CXD];
__device__ __half g_Wf16[4096 * 64];
__device__ __half g_Of16[CB * CJ * CH * CXD];

// ---------------- helpers ----------------
__device__ __forceinline__ uint32_t smem_u32(const void* p) {
    uint32_t a;
    asm("{ .reg .u64 t; cvta.to.shared.u64 t, %1; cvt.u32.u64 %0, t; }"
        : "=r"(a) : "l"(p));
    return a;
}
#define CP16(dst, src) \
    asm volatile("cp.async.cg.shared.global [%0], [%1], 16;" :: "r"(dst), "l"(src))
#define CP_COMMIT() asm volatile("cp.async.commit_group;" ::: "memory")
#define CP_WAIT(n)  asm volatile("cp.async.wait_group %0;" :: "n"(n) : "memory")

__device__ __forceinline__ void ldsm4(uint32_t a, uint32_t& r0, uint32_t& r1,
                                      uint32_t& r2, uint32_t& r3) {
    asm volatile("ldmatrix.sync.aligned.m8n8.x4.shared.b16 {%0,%1,%2,%3}, [%4];"
                 : "=r"(r0), "=r"(r1), "=r"(r2), "=r"(r3) : "r"(a));
}
__device__ __forceinline__ void ldsm4t(uint32_t a, uint32_t& r0, uint32_t& r1,
                                       uint32_t& r2, uint32_t& r3) {
    asm volatile("ldmatrix.sync.aligned.m8n8.x4.trans.shared.b16 {%0,%1,%2,%3}, [%4];"
                 : "=r"(r0), "=r"(r1), "=r"(r2), "=r"(r3) : "r"(a));
}
// fp16 mma
__device__ __forceinline__ void mma16816h(float* d, const uint32_t* a,
                                          uint32_t b0, uint32_t b1) {
    asm volatile(
        "mma.sync.aligned.m16n8k16.row.col.f32.f16.f16.f32 "
        "{%0,%1,%2,%3}, {%4,%5,%6,%7}, {%8,%9}, {%0,%1,%2,%3};"
        : "+f"(d[0]), "+f"(d[1]), "+f"(d[2]), "+f"(d[3])
        : "r"(a[0]), "r"(a[1]), "r"(a[2]), "r"(a[3]), "r"(b0), "r"(b1));
}

// ---------------- fused prep: k2 (blocks 0..255) + conversions + bias ----------------
// k2: K2[h][j][k] = s * W_q[k, h*64+e] k_lat[j,e] -> fp16, s = 0.125*log2(e)
__global__ void prep_all(const float* __restrict__ pos, const float* __restrict__ x,
                         const float* __restrict__ W_q, const float* __restrict__ k_lat,
                         const float* __restrict__ W_out,
                         const float* __restrict__ b_out, float* __restrict__ out) {
    __shared__ float sW[128 * 68];
    const int bi = blockIdx.x;
    const int tid = threadIdx.x;

    if (bi < 256) {
        // ---- k2 ----
        const int jblk = bi & 3, h = bi >> 2;
        const int lane = tid & 31, w = tid >> 5;
#pragma unroll
        for (int it = 0; it < 8; it++) {
            int f4 = tid + it * 256;
            int k = f4 >> 4, e4 = f4 & 15;
            float4 v = *(const float4*)(W_q + k * 4096 + h * 64 + e4 * 4);
            *(float4*)(sW + k * 68 + e4 * 4) = v;
        }
        __syncthreads();
#pragma unroll
        for (int jc = 0; jc < 8; jc++) {
            int j = jblk * 64 + w * 8 + jc;
            float a0 = 0.f, a1 = 0.f, a2 = 0.f, a3 = 0.f;
#pragma unroll
            for (int e = 0; e < 64; e += 4) {
                float4 kl = *(const float4*)(k_lat + j * 64 + e);
                float4 w0 = *(const float4*)(sW + (lane)      * 68 + e);
                float4 w1 = *(const float4*)(sW + (lane + 32) * 68 + e);
                float4 w2 = *(const float4*)(sW + (lane + 64) * 68 + e);
                float4 w3 = *(const float4*)(sW + (lane + 96) * 68 + e);
                a0 += w0.x * kl.x + w0.y * kl.y + w0.z * kl.z + w0.w * kl.w;
                a1 += w1.x * kl.x + w1.y * kl.y + w1.z * kl.z + w1.w * kl.w;
                a2 += w2.x * kl.x + w2.y * kl.y + w2.z * kl.z + w2.w * kl.w;
                a3 += w3.x * kl.x + w3.y * kl.y + w3.z * kl.z + w3.w * kl.w;
            }
            const float s = 0.18033688f;   // 0.125 * log2(e)
            int base = (h * CJ + j) * PD;
            g_Qf16[base + lane]      = __float2half_rn(a0 * s);
            g_Qf16[base + lane + 32] = __float2half_rn(a1 * s);
            g_Qf16[base + lane + 64] = __float2half_rn(a2 * s);
            g_Qf16[base + lane + 96] = __float2half_rn(a3 * s);
        }
    } else if (bi < 1280) {
        int i = (bi - 256) * 256 + tid;          // 262144 float4s of pos
        float4 v = ((const float4*)pos)[i];
        ((__half2*)g_posF16)[i * 2]     = __floats2half2_rn(v.x, v.y);
        ((__half2*)g_posF16)[i * 2 + 1] = __floats2half2_rn(v.z, v.w);
    } else if (bi < 1792) {
        int i = (bi - 1280) * 256 + tid;         // 131072 float4s of x
        float4 v = ((const float4*)x)[i];
        ((__half2*)g_xF16)[i * 2]     = __floats2half2_rn(v.x, v.y);
        ((__half2*)g_xF16)[i * 2 + 1] = __floats2half2_rn(v.z, v.w);
    } else if (bi < 2048) {
        int i = (bi - 1792) * 256 + tid;         // 65536 float4s of W_out
        float4 v = ((const float4*)W_out)[i];
        ((__half2*)g_Wf16)[i * 2]     = __floats2half2_rn(v.x, v.y);
        ((__half2*)g_Wf16)[i * 2 + 1] = __floats2half2_rn(v.z, v.w);
    } else {
        int idx = (bi - 2048) * 256 + tid;       // 131072 out elements
        out[idx] = b_out[idx & 63];
    }
}

// ---------------- attention: all-fp16 single-pass S and PV ----------------
#define KROW 272
#define XROW 144
#define KSTG 34816                 // 128 * 272
#define XSTG 18432                 // 128 * 144 (single fp16)
#define OKST(s) ((s) * KSTG)
#define OXST(s) (104448 + (s) * XSTG)
#define O_Q   159744               // dedicated Q region
#define SMEM_BYTES 194560          // O_Q + KSTG

__device__ __forceinline__ void prefetch_g(uint32_t sb, int st, int b, int n0, int tid) {
    uint32_t kbase = sb + OKST(st);
    const __half* kp = g_posF16 + (size_t)(b * CN + n0) * PD;
#pragma unroll
    for (int it = 0; it < 4; it++) {
        int idx = tid + it * 512;
        int row = idx >> 4, q = idx & 15;
        CP16(kbase + row * KROW + q * 16, kp + row * PD + q * 8);
    }
    uint32_t xbase = sb + OXST(st);
    const __half* xp = g_xF16 + (size_t)(b * CN + n0) * CXD;
#pragma unroll
    for (int it = 0; it < 2; it++) {
        int idx = tid + it * 512;
        int row = idx >> 3, q = idx & 7;
        CP16(xbase + row * XROW + q * 16, xp + row * CXD + q * 8);
    }
}

__global__ __launch_bounds__(512, 1)
void attn_kernel() {
    extern __shared__ char smc[];
    const uint32_t sb = smem_u32(smc);
    const int tid = threadIdx.x;
    const int lane = tid & 31, w = tid >> 5;
    const int wm = w & 7, half = w >> 3;
    const int jt = blockIdx.x, h = blockIdx.y, b = blockIdx.z;
    const int m0 = wm * 16;
    const int g = lane >> 2, t = lane & 3;

    const int arow = (lane & 7) + ((lane >> 3) & 1) * 8;
    const int acol = ((lane >> 4) & 1) * 16;
    const int brow = (lane & 7) + ((lane >> 4) & 1) * 8;
    const int bcol = ((lane >> 3) & 1) * 16;
    const int xrow = (lane & 7) + ((lane >> 3) & 1) * 8;
    const int xcol = ((lane >> 4) & 1) * 16;

    // ---- prologue: stage Q, prefetch G0/G1 ----
    {
        const __half* qp = g_Qf16 + (size_t)(h * CJ + jt * 128) * PD;
#pragma unroll
        for (int it = 0; it < 4; it++) {
            int idx = tid + it * 512;
            int row = idx >> 4, q = idx & 15;
            CP16(sb + O_Q + row * KROW + q * 16, qp + row * PD + q * 8);
        }
        CP_COMMIT();
        prefetch_g(sb, 0, b, 0, tid);
        CP_COMMIT();
        prefetch_g(sb, 1, b, 128, tid);
        CP_COMMIT();
    }
    CP_WAIT(2);
    __syncthreads();
    uint32_t qA[8][4];
    {
        uint32_t qb = sb + O_Q + (m0 + arow) * KROW + acol;
#pragma unroll
        for (int ks = 0; ks < 8; ks++)
            ldsm4(qb + ks * 32, qA[ks][0], qA[ks][1], qA[ks][2], qA[ks][3]);
    }

    float oacc[8][4];
#pragma unroll
    for (int i = 0; i < 8; i++)
#pragma unroll
        for (int r = 0; r < 4; r++) oacc[i][r] = 0.f;
    float rs0 = 0.f, rs1 = 0.f;

    for (int ch = 0; ch < 8; ch++) {
        if (ch < 7) { CP_WAIT(1); } else { CP_WAIT(0); }
        __syncthreads();     // data visible; all warps past chunk ch-1
        if (ch + 2 < 8) {
            prefetch_g(sb, (ch + 2) % 3, b, (ch + 2) * 128, tid);
            CP_COMMIT();
        }

        const uint32_t kb = sb + OKST(ch % 3) + (half * 64 + brow) * KROW + bcol;
        const uint32_t xbase = sb + OXST(ch % 3);

        float sc[2][8];

        // S slab 0
#pragma unroll
        for (int r = 0; r < 8; r++) sc[0][r] = 0.f;
#pragma unroll
        for (int ks = 0; ks < 8; ks++) {
            uint32_t k0, k1, k2, k3;
            ldsm4(kb + ks * 32, k0, k1, k2, k3);
            mma16816h(sc[0],     qA[ks], k0, k1);
            mma16816h(sc[0] + 4, qA[ks], k2, k3);
        }

#pragma unroll
        for (int np = 0; np < 4; np++) {
            const int cur = np & 1, nxt = cur ^ 1;
            // issue next slab's S-MMAs first: tensor stays busy during exp(np)
            if (np < 3) {
#pragma unroll
                for (int r = 0; r < 8; r++) sc[nxt][r] = 0.f;
#pragma unroll
                for (int ks = 0; ks < 8; ks++) {
                    uint32_t k0, k1, k2, k3;
                    ldsm4(kb + (np + 1) * (16 * KROW) + ks * 32, k0, k1, k2, k3);
                    mma16816h(sc[nxt],     qA[ks], k0, k1);
                    mma16816h(sc[nxt] + 4, qA[ks], k2, k3);
                }
            }
            // epilogue of slab np: exp2 -> fp16 P frags (log2e folded in Q scale)
            float p0 = exp2f(sc[cur][0]);
            float p1 = exp2f(sc[cur][1]);
            float p2 = exp2f(sc[cur][2]);
            float p3 = exp2f(sc[cur][3]);
            float p4 = exp2f(sc[cur][4]);
            float p5 = exp2f(sc[cur][5]);
            float p6 = exp2f(sc[cur][6]);
            float p7 = exp2f(sc[cur][7]);
            rs0 += p0 + p1 + p4 + p5;
            rs1 += p2 + p3 + p6 + p7;
            uint32_t ph[4];
            __half2 h0 = __floats2half2_rn(p0, p1);
            __half2 h1 = __floats2half2_rn(p2, p3);
            __half2 h2 = __floats2half2_rn(p4, p5);
            __half2 h3 = __floats2half2_rn(p6, p7);
            ph[0] = *reinterpret_cast<uint32_t*>(&h0);
            ph[1] = *reinterpret_cast<uint32_t*>(&h1);
            ph[2] = *reinterpret_cast<uint32_t*>(&h2);
            ph[3] = *reinterpret_cast<uint32_t*>(&h3);
            // PV single pass fp16
            uint32_t xb = xbase + (half * 64 + np * 16 + xrow) * XROW + xcol;
#pragma unroll
            for (int xt = 0; xt < 4; xt++) {
                uint32_t x0, x1, x2, x3;
                ldsm4t(xb + xt * 32, x0, x1, x2, x3);
                mma16816h(oacc[2 * xt],     ph, x0, x1);
                mma16816h(oacc[2 * xt + 1], ph, x2, x3);
            }
        }
    }
    __syncthreads();   // compute done; low smem reusable for exchange

    // ---- pair reduction across warp halves ----
    rs0 += __shfl_xor_sync(0xffffffffu, rs0, 1);
    rs0 += __shfl_xor_sync(0xffffffffu, rs0, 2);
    rs1 += __shfl_xor_sync(0xffffffffu, rs1, 1);
    rs1 += __shfl_xor_sync(0xffffffffu, rs1, 2);

    float* exO = (float*)smc;                 // [8][32][32]
    float* exR = (float*)(smc + 32768);       // [8][16]
    if (half == 1) {
#pragma unroll
        for (int xt = 0; xt < 8; xt++) {
#pragma unroll
            for (int r = 0; r < 4; r++)
                exO[(wm * 32 + lane) * 32 + xt * 4 + r] = oacc[xt][r];
        }
        if (t == 0) {
            exR[wm * 16 + g] = rs0;
            exR[wm * 16 + 8 + g] = rs1;
        }
    }
    __syncthreads();
    if (half == 0) {
        float inv0 = 1.0f / (rs0 + exR[wm * 16 + g]);
        float inv1 = 1.0f / (rs1 + exR[wm * 16 + 8 + g]);
        int j0 = jt * 128 + m0 + g;
        __half* ob = g_Of16 + (size_t)(b * CJ + j0) * (CH * CXD) + h * CXD;
#pragma unroll
        for (int xt = 0; xt < 8; xt++) {
            int col = xt * 8 + 2 * t;
            float b0 = exO[(wm * 32 + lane) * 32 + xt * 4 + 0];
            float b1 = exO[(wm * 32 + lane) * 32 + xt * 4 + 1];
            float b2 = exO[(wm * 32 + lane) * 32 + xt * 4 + 2];
            float b3 = exO[(wm * 32 + lane) * 32 + xt * 4 + 3];
            __half2 v0 = __floats2half2_rn((oacc[xt][0] + b0) * inv0,
                                           (oacc[xt][1] + b1) * inv0);
            __half2 v1 = __floats2half2_rn((oacc[xt][2] + b2) * inv1,
                                           (oacc[xt][3] + b3) * inv1);
            *(__half2*)(ob + col) = v0;
            *(__half2*)(ob + 8 * (CH * CXD) + col) = v1;
        }
    }
}

// ---------------- out = O @ W + b (fp16 tensor cores, k-split x16) ----------------
#define AROW 144
#define WROW 144
#define OA_BYTES (128 * AROW)      // 18432
#define OW_BYTES (64 * WROW)       // 9216
#define OSTG (OA_BYTES + OW_BYTES) // 27648
#define OUT_SMEM_BYTES (2 * OSTG)  // 55296

__device__ __forceinline__ void out_prefetch(uint32_t sb, int st, int r0, int k0, int tid) {
    uint32_t ab = sb + st * OSTG;
#pragma unroll
    for (int it = 0; it < 4; it++) {
        int idx = tid + it * 256;        // 1024: 128 rows x 8 x 16B
        int row = idx >> 3, q = idx & 7;
        CP16(ab + row * AROW + q * 16, g_Of16 + (size_t)(r0 + row) * 4096 + k0 + q * 8);
    }
    uint32_t wb = ab + OA_BYTES;
#pragma unroll
    for (int it = 0; it < 2; it++) {
        int idx = tid + it * 256;        // 512: 64 k-rows x 8 x 16B
        int row = idx >> 3, q = idx & 7;
        CP16(wb + row * WROW + q * 16, g_Wf16 + (size_t)(k0 + row) * 64 + q * 8);
    }
}

__global__ __launch_bounds__(256, 1)
void out_kernel(float* __restrict__ out) {
    extern __shared__ char osmc[];
    const uint32_t sb = smem_u32(osmc);
    const int r0 = blockIdx.x * 128, ksl = blockIdx.y;   // grid (16, 16)
    const int tid = threadIdx.x;
    const int lane = tid & 31, w = tid >> 5;
    const int m0 = w * 16;
    const int g = lane >> 2, t = lane & 3;

    const int arow = (lane & 7) + ((lane >> 3) & 1) * 8;
    const int acol = ((lane >> 4) & 1) * 16;
    const int xrow = (lane & 7) + ((lane >> 3) & 1) * 8;
    const int xcol = ((lane >> 4) & 1) * 16;

    out_prefetch(sb, 0, r0, ksl * 256, tid);
    CP_COMMIT();

    float oacc[8][4];
#pragma unroll
    for (int i = 0; i < 8; i++)
#pragma unroll
        for (int r = 0; r < 4; r++) oacc[i][r] = 0.f;

    for (int sub = 0; sub < 4; sub++) {
        const int st = sub & 1;
        CP_WAIT(0);
        __syncthreads();
        if (sub + 1 < 4) {
            out_prefetch(sb, st ^ 1, r0, ksl * 256 + (sub + 1) * 64, tid);
            CP_COMMIT();
        }
        uint32_t abase = sb + st * OSTG + (m0 + arow) * AROW + acol;
        uint32_t wbase = sb + st * OSTG + OA_BYTES + xrow * WROW + xcol;
#pragma unroll
        for (int ks = 0; ks < 4; ks++) {
            uint32_t A[4];
            ldsm4(abase + ks * 32, A[0], A[1], A[2], A[3]);
#pragma unroll
            for (int ct = 0; ct < 4; ct++) {
                uint32_t x0, x1, x2, x3;
                ldsm4t(wbase + ks * (16 * WROW) + ct * 32, x0, x1, x2, x3);
                mma16816h(oacc[2 * ct],     A, x0, x1);
                mma16816h(oacc[2 * ct + 1], A, x2, x3);
            }
        }
        __syncthreads();
    }

    int r = r0 + m0 + g;
#pragma unroll
    for (int i = 0; i < 8; i++) {
        int c = i * 8 + 2 * t;
        atomicAdd(out + (size_t)r * 64 + c,           oacc[i][0]);
        atomicAdd(out + (size_t)r * 64 + c + 1,       oacc[i][1]);
        atomicAdd(out + (size_t)(r + 8) * 64 + c,     oacc[i][2]);
        atomicAdd(out + (size_t)(r + 8) * 64 + c + 1, oacc[i][3]);
    }
}

// ---------------------------------------------------------------------------
extern "C" void kernel_launch(void* const* d_in, const int* in_sizes, int n_in,
                              void* d_out, int out_size) {
    (void)in_sizes; (void)n_in; (void)out_size;
    const float* pos   = (const float*)d_in[0];
    const float* x     = (const float*)d_in[1];
    const float* W_q   = (const float*)d_in[2];
    const float* k_lat = (const float*)d_in[3];
    const float* W_out = (const float*)d_in[4];
    const float* b_out = (const float*)d_in[5];
    float* out = (float*)d_out;

    cudaFuncSetAttribute(attn_kernel, cudaFuncAttributeMaxDynamicSharedMemorySize,
                         SMEM_BYTES);
    cudaFuncSetAttribute(out_kernel, cudaFuncAttributeMaxDynamicSharedMemorySize,
                         OUT_SMEM_BYTES);

    prep_all<<<2560, 256>>>(pos, x, W_q, k_lat, W_out, b_out, out);
    attn_kernel<<<dim3(2, CH, CB), 512, SMEM_BYTES>>>();
    out_kernel<<<dim3(16, 16), 256, OUT_SMEM_BYTES>>>(out);
}